// round 1
// baseline (speedup 1.0000x reference)
#include <cuda_runtime.h>
#include <cstdint>

#define Bq 8
#define Hq 128
#define Wq 128
#define Cq 128
#define Fq 128
#define KHW 9

#define TH 8
#define TW 8
#define CCHUNK 32

// Scratch for modulated + demodulated weights: [b][khw][c][f], f fastest.
__device__ float g_wmod[Bq * KHW * Cq * Fq];

// ---------------------------------------------------------------------------
// Kernel 1: modulate + demodulate weights.
// grid = (F, B), block = 128 threads (one per input channel c).
// w[b,k,c,f] = kernel[k,c,f] * (style[b,c]+1) / sqrt(sum_{k,c} (...)^2 + 1e-8)
// ---------------------------------------------------------------------------
__global__ __launch_bounds__(128) void modw_kernel(const float* __restrict__ style,
                                                   const float* __restrict__ kern)
{
    const int f = blockIdx.x;
    const int b = blockIdx.y;
    const int c = threadIdx.x;

    const float s = style[b * Cq + c] + 1.0f;

    float v[KHW];
    float sq = 0.0f;
#pragma unroll
    for (int k = 0; k < KHW; k++) {
        float kv = kern[(k * Cq + c) * Fq + f];
        float vv = kv * s;
        v[k] = vv;
        sq += vv * vv;
    }

    // Reduce sq over the 128 threads (sum over c; k already summed per-thread).
    __shared__ float red[4];
#pragma unroll
    for (int o = 16; o > 0; o >>= 1)
        sq += __shfl_xor_sync(0xffffffffu, sq, o);
    if ((c & 31) == 0) red[c >> 5] = sq;
    __syncthreads();
    float tot = red[0] + red[1] + red[2] + red[3];

    float xarg = tot + 1e-8f;
    float r = rsqrtf(xarg);
    // one Newton iteration for near-full fp32 precision
    r = r * (1.5f - 0.5f * xarg * r * r);

#pragma unroll
    for (int k = 0; k < KHW; k++)
        g_wmod[((b * KHW + k) * Cq + c) * Fq + f] = v[k] * r;
}

// ---------------------------------------------------------------------------
// Kernel 2: 3x3 SAME conv, per-batch weights.
// grid = (W/TW, H/TH, B), block = 256 threads.
// Block output tile: TH x TW spatial x all F=128 outputs.
// Thread tile: 4 spatial x 8 f -> 32 accumulators.
// ---------------------------------------------------------------------------
__global__ __launch_bounds__(256) void conv_kernel(const float* __restrict__ x,
                                                   float* __restrict__ out)
{
    __shared__ float sx[TH + 2][TW + 2][CCHUNK];   // 10*10*32*4 = 12.8 KB
    __shared__ float sw_[CCHUNK][Fq];              // 32*128*4  = 16 KB

    const int tid = threadIdx.x;
    const int b  = blockIdx.z;
    const int h0 = blockIdx.y * TH;
    const int w0 = blockIdx.x * TW;

    const int f_grp = tid & 15;          // 16 groups of 8 f
    const int s_grp = tid >> 4;          // 16 groups of 4 spatial
    const int fb = f_grp * 8;

    float acc[4][8];
#pragma unroll
    for (int i = 0; i < 4; i++)
#pragma unroll
        for (int j = 0; j < 8; j++) acc[i][j] = 0.0f;

    // spatial coords of this thread's 4 outputs (within tile)
    int shh[4], sww[4];
#pragma unroll
    for (int si = 0; si < 4; si++) {
        int sp = s_grp * 4 + si;
        shh[si] = sp >> 3;
        sww[si] = sp & 7;
    }

    for (int cc = 0; cc < Cq; cc += CCHUNK) {
        __syncthreads();
        // ---- load 10x10xCCHUNK halo x-tile (zero-padded) via float4 ----
        // 10*10*(32/4) = 800 float4 loads over 256 threads
        for (int i = tid; i < (TH + 2) * (TW + 2) * (CCHUNK / 4); i += 256) {
            int hh  = i / ((TW + 2) * (CCHUNK / 4));
            int rem = i % ((TW + 2) * (CCHUNK / 4));
            int ww  = rem / (CCHUNK / 4);
            int c4  = rem % (CCHUNK / 4);
            int gh = h0 - 1 + hh;
            int gw = w0 - 1 + ww;
            float4 val = make_float4(0.f, 0.f, 0.f, 0.f);
            if (gh >= 0 && gh < Hq && gw >= 0 && gw < Wq) {
                val = *(const float4*)&x[((((size_t)b * Hq + gh) * Wq + gw) * Cq) + cc + c4 * 4];
            }
            *(float4*)&sx[hh][ww][c4 * 4] = val;
        }

        for (int khw = 0; khw < KHW; khw++) {
            __syncthreads();
            // ---- load weight slab [CCHUNK][F] for this tap ----
            const float4* wg = (const float4*)&g_wmod[((b * KHW + khw) * Cq + cc) * Fq];
            float4* swv = (float4*)sw_;
#pragma unroll 4
            for (int i = tid; i < CCHUNK * Fq / 4; i += 256)
                swv[i] = wg[i];
            __syncthreads();

            const int kh = khw / 3;
            const int kw = khw % 3;

            const float* xb0 = &sx[shh[0] + kh][sww[0] + kw][0];
            const float* xb1 = &sx[shh[1] + kh][sww[1] + kw][0];
            const float* xb2 = &sx[shh[2] + kh][sww[2] + kw][0];
            const float* xb3 = &sx[shh[3] + kh][sww[3] + kw][0];

#pragma unroll 8
            for (int cl = 0; cl < CCHUNK; cl++) {
                float4 wv0 = *(const float4*)&sw_[cl][fb];
                float4 wv1 = *(const float4*)&sw_[cl][fb + 4];
                float xv0 = xb0[cl];
                float xv1 = xb1[cl];
                float xv2 = xb2[cl];
                float xv3 = xb3[cl];

                acc[0][0] += xv0 * wv0.x; acc[0][1] += xv0 * wv0.y;
                acc[0][2] += xv0 * wv0.z; acc[0][3] += xv0 * wv0.w;
                acc[0][4] += xv0 * wv1.x; acc[0][5] += xv0 * wv1.y;
                acc[0][6] += xv0 * wv1.z; acc[0][7] += xv0 * wv1.w;

                acc[1][0] += xv1 * wv0.x; acc[1][1] += xv1 * wv0.y;
                acc[1][2] += xv1 * wv0.z; acc[1][3] += xv1 * wv0.w;
                acc[1][4] += xv1 * wv1.x; acc[1][5] += xv1 * wv1.y;
                acc[1][6] += xv1 * wv1.z; acc[1][7] += xv1 * wv1.w;

                acc[2][0] += xv2 * wv0.x; acc[2][1] += xv2 * wv0.y;
                acc[2][2] += xv2 * wv0.z; acc[2][3] += xv2 * wv0.w;
                acc[2][4] += xv2 * wv1.x; acc[2][5] += xv2 * wv1.y;
                acc[2][6] += xv2 * wv1.z; acc[2][7] += xv2 * wv1.w;

                acc[3][0] += xv3 * wv0.x; acc[3][1] += xv3 * wv0.y;
                acc[3][2] += xv3 * wv0.z; acc[3][3] += xv3 * wv0.w;
                acc[3][4] += xv3 * wv1.x; acc[3][5] += xv3 * wv1.y;
                acc[3][6] += xv3 * wv1.z; acc[3][7] += xv3 * wv1.w;
            }
        }
    }

    // ---- write outputs: 4 spatial x 8 f as two float4 each ----
#pragma unroll
    for (int si = 0; si < 4; si++) {
        int gh = h0 + shh[si];
        int gw = w0 + sww[si];
        float* op = &out[(((size_t)b * Hq + gh) * Wq + gw) * Fq + fb];
        float4 o0 = make_float4(acc[si][0], acc[si][1], acc[si][2], acc[si][3]);
        float4 o1 = make_float4(acc[si][4], acc[si][5], acc[si][6], acc[si][7]);
        *(float4*)op = o0;
        *(float4*)(op + 4) = o1;
    }
}

// ---------------------------------------------------------------------------
extern "C" void kernel_launch(void* const* d_in, const int* in_sizes, int n_in,
                              void* d_out, int out_size)
{
    const float* x     = (const float*)d_in[0];   // (8,128,128,128) NHWC
    const float* style = (const float*)d_in[1];   // (8,128)
    const float* kern  = (const float*)d_in[2];   // (3,3,128,128)
    float* out = (float*)d_out;                   // (8,128,128,128) NHWC

    (void)in_sizes; (void)n_in; (void)out_size;

    dim3 gridM(Fq, Bq);
    modw_kernel<<<gridM, 128>>>(style, kern);

    dim3 gridC(Wq / TW, Hq / TH, Bq);
    conv_kernel<<<gridC, 256>>>(x, out);
}

// round 3
// speedup vs baseline: 4.3473x; 4.3473x over previous
#include <cuda_runtime.h>
#include <cstdint>

#define Bq 8
#define Hq 128
#define Wq 128
#define Cq 128
#define Fq 128

// ---------------------------------------------------------------------------
// Modulated+demodulated weights in MMA-friendly layout:
//   g_wmod[((b*9 + tap)*4 + cc)*4096 + kk*128 + f]   (kk = c%32, cc = c/32)
// i.e. per (b,tap,cc): a 16 KB slab, k-major rows of 128 f.
// Values are pre-rounded to tf32 (cvt.rna).
// ---------------------------------------------------------------------------
__device__ float g_wmod[Bq * 9 * Cq * Fq];

__global__ __launch_bounds__(256) void modw_kernel(const float* __restrict__ style,
                                                   const float* __restrict__ kern)
{
    // grid: (4 f-groups, B).  block: 256 = 8 c-slices x 32 f.
    const int fg = blockIdx.x;
    const int b  = blockIdx.y;
    const int f0 = fg * 32;
    const int tid = threadIdx.x;
    const int fi = tid & 31;
    const int cp = tid >> 5;          // 0..7

    __shared__ float ssty[Cq];
    __shared__ float red[8][32];
    __shared__ float rr[32];

    if (tid < Cq) ssty[tid] = style[b * Cq + tid] + 1.0f;
    __syncthreads();

    // stage 1: per-f sum of squares over (k, c)
    float sq = 0.0f;
    for (int k = 0; k < 9; k++) {
#pragma unroll 4
        for (int j = 0; j < 16; j++) {
            int c = cp + j * 8;
            float kv = kern[(k * Cq + c) * Fq + f0 + fi] * ssty[c];
            sq += kv * kv;
        }
    }
    red[cp][fi] = sq;
    __syncthreads();
    if (tid < 32) {
        float t = 0.0f;
#pragma unroll
        for (int j = 0; j < 8; j++) t += red[j][tid];
        float xarg = t + 1e-8f;
        float r = rsqrtf(xarg);
        r = r * (1.5f - 0.5f * xarg * r * r);   // Newton -> fp32 accuracy
        rr[tid] = r;
    }
    __syncthreads();

    // stage 2: write normalized weights, tf32-rounded, new layout
    for (int i = tid; i < 9 * Cq * 32; i += 256) {
        int k   = i >> 12;            // /4096
        int rem = i & 4095;
        int c   = rem >> 5;
        int fl  = rem & 31;
        float v = kern[(k * Cq + c) * Fq + f0 + fl] * ssty[c] * rr[fl];
        uint32_t bits;
        asm("cvt.rna.tf32.f32 %0, %1;" : "=r"(bits) : "f"(v));
        g_wmod[(((b * 9 + k) * 4 + (c >> 5)) * 32 + (c & 31)) * Fq + f0 + fl] =
            __uint_as_float(bits);
    }
}

// ---------------------------------------------------------------------------
// Conv kernel: CTA = (b, output row h0).  GEMM M=128(w) x N=128(f), K=1152.
// mma.sync.m16n8k8 tf32.  8 warps = 4(m) x 2(n), warp tile 32x64.
// ---------------------------------------------------------------------------
#define XS_WORDS 12480                 // 3 rows * 130 pos * 32 c floats
#define WS_WORDS 4096                  // 32 k * 128 f floats
#define SMEM_WORDS (2 * XS_WORDS + 2 * WS_WORDS)
#define SMEM_BYTES (SMEM_WORDS * 4)    // 132608

__device__ __forceinline__ void cp_async16(uint32_t daddr, const void* saddr, int srcsz) {
    asm volatile("cp.async.cg.shared.global [%0], [%1], 16, %2;"
                 :: "r"(daddr), "l"(saddr), "r"(srcsz) : "memory");
}
__device__ __forceinline__ void cp_commit() {
    asm volatile("cp.async.commit_group;" ::: "memory");
}
__device__ __forceinline__ void cp_wait1() {
    asm volatile("cp.async.wait_group 1;" ::: "memory");
}

__device__ __forceinline__ void mma_tf32(float& c0, float& c1, float& c2, float& c3,
                                         uint32_t a0, uint32_t a1, uint32_t a2, uint32_t a3,
                                         uint32_t b0, uint32_t b1) {
    asm volatile("mma.sync.aligned.m16n8k8.row.col.f32.tf32.tf32.f32 "
                 "{%0,%1,%2,%3}, {%4,%5,%6,%7}, {%8,%9}, {%0,%1,%2,%3};"
                 : "+f"(c0), "+f"(c1), "+f"(c2), "+f"(c3)
                 : "r"(a0), "r"(a1), "r"(a2), "r"(a3), "r"(b0), "r"(b1));
}

__global__ __launch_bounds__(256, 1) void conv_tc_kernel(const float* __restrict__ x,
                                                         float* __restrict__ out)
{
    extern __shared__ float sm[];
    uint32_t smbase;
    asm("{ .reg .u64 t; cvta.to.shared.u64 t, %1; cvt.u32.u64 %0, t; }"
        : "=r"(smbase) : "l"(sm));

    const int tid = threadIdx.x;
    const int lane = tid & 31;
    const int wid  = tid >> 5;
    const int g    = lane >> 2;       // groupID
    const int tig  = lane & 3;        // thread-in-group
    const int warpM = wid & 3;        // 0..3 (m tiles of 32)
    const int warpN = wid >> 2;       // 0..1 (n tiles of 64)

    const int h0 = blockIdx.x;
    const int b  = blockIdx.y;

    float acc[2][8][4];
#pragma unroll
    for (int mt = 0; mt < 2; mt++)
#pragma unroll
        for (int nt = 0; nt < 8; nt++)
#pragma unroll
            for (int q = 0; q < 4; q++) acc[mt][nt][q] = 0.0f;

    // ---- fill helpers ----
    // x band for c-chunk cc into buffer bb: xs[r][p][kk], word swizzle kk ^ ((p&7)*4)
    auto fill_band = [&](int cc, int bb) {
        const float* xb = x + ((size_t)b * Hq) * Wq * Cq + cc * 32;
        for (int i = tid; i < 3 * 130 * 8; i += 256) {
            int r   = i / 1040;
            int rem = i - r * 1040;
            int p   = rem >> 3;
            int kk4 = rem & 7;
            int gh = h0 - 1 + r;
            int gw = p - 1;
            int valid = (gh >= 0 && gh < Hq && gw >= 0 && gw < Wq) ? 16 : 0;
            int ghc = gh < 0 ? 0 : (gh > Hq - 1 ? Hq - 1 : gh);
            int gwc = gw < 0 ? 0 : (gw > Wq - 1 ? Wq - 1 : gw);
            const float* src = xb + ((size_t)ghc * Wq + gwc) * Cq + kk4 * 4;
            uint32_t w = bb * XS_WORDS + (r * 130 + p) * 32 + ((kk4 * 4) ^ ((p & 7) * 4));
            cp_async16(smbase + w * 4, src, valid);
        }
    };
    // weight slab (b,tap,cc) into buffer bb: ws[k][f], word swizzle f ^ ((k&3)*8)
    auto fill_ws = [&](int tap, int cc, int bb) {
        const float* src0 = g_wmod + (((size_t)(b * 9 + tap) * 4 + cc)) * 4096;
        for (int i = tid; i < 1024; i += 256) {
            int kk = i >> 5;
            int f4 = i & 31;
            uint32_t w = 2 * XS_WORDS + bb * WS_WORDS + kk * 128 + ((f4 * 4) ^ ((kk & 3) * 8));
            cp_async16(smbase + w * 4, src0 + kk * 128 + f4 * 4, 16);
        }
    };

    // ---- prologue ----
    fill_band(0, 0);
    fill_ws(0, 0, 0);
    cp_commit();

    for (int it = 0; it < 36; it++) {
        const int cc  = it / 9;
        const int tap = it - cc * 9;
        const int kh = tap / 3;
        const int kw = tap - kh * 3;

        __syncthreads();            // prev iter's reads of prefetch buffers done
        if (it + 1 < 36) {
            int itn = it + 1;
            int ccn = itn / 9;
            fill_ws(itn - ccn * 9, ccn, itn & 1);
            if (tap == 0 && cc + 1 < 4) fill_band(cc + 1, (cc + 1) & 1);
        }
        cp_commit();
        cp_wait1();                 // ws(it) + band(cc) ready
        __syncthreads();

        const int xb = (cc & 1) * XS_WORDS + kh * 130 * 32;
        const int wb = 2 * XS_WORDS + (it & 1) * WS_WORDS;

        // m rows for the two m-tiles
        const int mA = warpM * 32 + g;          // mt0 rows g, g+8
        const int mB = mA + 16;                 // mt1 rows
        const int pA0 = mA + kw,  pA1 = pA0 + 8;
        const int pB0 = mB + kw,  pB1 = pB0 + 8;
        const int baseA0 = xb + pA0 * 32, mkA0 = (pA0 & 7) * 4;
        const int baseA1 = xb + pA1 * 32, mkA1 = (pA1 & 7) * 4;
        const int baseB0 = xb + pB0 * 32, mkB0 = (pB0 & 7) * 4;
        const int baseB1 = xb + pB1 * 32, mkB1 = (pB1 & 7) * 4;

#pragma unroll
        for (int ks = 0; ks < 4; ks++) {
            const int k0 = ks * 8 + tig;
            uint32_t a0[2], a1[2], a2[2], a3[2];
            a0[0] = __float_as_uint(sm[baseA0 + (k0 ^ mkA0)]);
            a2[0] = __float_as_uint(sm[baseA0 + ((k0 + 4) ^ mkA0)]);
            a1[0] = __float_as_uint(sm[baseA1 + (k0 ^ mkA1)]);
            a3[0] = __float_as_uint(sm[baseA1 + ((k0 + 4) ^ mkA1)]);
            a0[1] = __float_as_uint(sm[baseB0 + (k0 ^ mkB0)]);
            a2[1] = __float_as_uint(sm[baseB0 + ((k0 + 4) ^ mkB0)]);
            a1[1] = __float_as_uint(sm[baseB1 + (k0 ^ mkB1)]);
            a3[1] = __float_as_uint(sm[baseB1 + ((k0 + 4) ^ mkB1)]);

            const int brow = wb + k0 * 128;
            const int fx = (warpN * 64 + g) ^ (tig * 8);
#pragma unroll
            for (int nt = 0; nt < 8; nt++) {
                // n0 = warpN*64 + nt*8; nt*8 only touches bits >=3, XOR mask is tig*8 (bits 3..4)
                // f ^ (tig*8) = ((warpN*64 + g) ^ (tig*8)) + nt*8 only when no carry overlap;
                // safer: recompute exactly:
                uint32_t bw = brow + (((warpN * 64 + nt * 8 + g) ^ (tig * 8)));
                uint32_t b0 = __float_as_uint(sm[bw]);
                uint32_t b1 = __float_as_uint(sm[bw + 512]);
                mma_tf32(acc[0][nt][0], acc[0][nt][1], acc[0][nt][2], acc[0][nt][3],
                         a0[0], a1[0], a2[0], a3[0], b0, b1);
                mma_tf32(acc[1][nt][0], acc[1][nt][1], acc[1][nt][2], acc[1][nt][3],
                         a0[1], a1[1], a2[1], a3[1], b0, b1);
            }
            (void)fx;
        }
    }

    // ---- epilogue: direct STG from accumulators ----
    float* ob = out + (((size_t)b * Hq + h0) * Wq) * Fq;
#pragma unroll
    for (int mt = 0; mt < 2; mt++) {
        const int m = warpM * 32 + mt * 16 + g;
#pragma unroll
        for (int nt = 0; nt < 8; nt++) {
            const int f = warpN * 64 + nt * 8 + tig * 2;
            float2 v0 = make_float2(acc[mt][nt][0], acc[mt][nt][1]);
            float2 v1 = make_float2(acc[mt][nt][2], acc[mt][nt][3]);
            *(float2*)(ob + (size_t)m * Fq + f) = v0;
            *(float2*)(ob + (size_t)(m + 8) * Fq + f) = v1;
        }
    }
}

// ---------------------------------------------------------------------------
extern "C" void kernel_launch(void* const* d_in, const int* in_sizes, int n_in,
                              void* d_out, int out_size)
{
    const float* x     = (const float*)d_in[0];   // (8,128,128,128) NHWC
    const float* style = (const float*)d_in[1];   // (8,128)
    const float* kern  = (const float*)d_in[2];   // (3,3,128,128)
    float* out = (float*)d_out;

    (void)in_sizes; (void)n_in; (void)out_size;

    cudaFuncSetAttribute(conv_tc_kernel, cudaFuncAttributeMaxDynamicSharedMemorySize, SMEM_BYTES);

    dim3 gridM(4, Bq);
    modw_kernel<<<gridM, 256>>>(style, kern);

    dim3 gridC(Hq, Bq);                            // 128 rows x 8 batch = 1024 CTAs
    conv_tc_kernel<<<gridC, 256, SMEM_BYTES>>>(x, out);
}